// round 12
// baseline (speedup 1.0000x reference)
#include <cuda_runtime.h>
#include <cstdint>

// Problem constants
#define N_NODES 8192
#define HALF    4096
#define T_DIM   256
#define F_DIM   128
#define C_DIM   32
#define NT_TOT  (N_NODES * T_DIM)
#define MAXDEG  512
#define LN_EPS  1e-5f
#define WSTRIDE 260

// ---------------- device scratch ----------------
__device__ float g_W1[C_DIM * T_DIM];
__device__ float g_W2[C_DIM * T_DIM];
__device__ float g_bS[C_DIM];
__device__ float g_w1sum[C_DIM];
__device__ float g_w2sum[C_DIM];
__device__ float g_stats[2];
__device__ float g_part[2048];
__device__ int   g_arr1 = 0;
__device__ int   g_arr2 = 0;
__device__ unsigned g_mask[N_NODES * 256];
__device__ float g_Y[N_NODES * C_DIM];
__device__ float g_Z[N_NODES * C_DIM];
__device__ int   g_cnt[N_NODES];
__device__ float g_dinv[N_NODES];
__device__ float g_s[N_NODES * C_DIM];
__device__ float g_w[N_NODES * C_DIM];      // dinv_j * s_j
__device__ float2 g_aux[N_NODES];           // (dinv_i, nsq_i)
__device__ float g_diag[N_NODES];           // dinv_i^2 * nsq_i
__device__ float g_rownum[N_NODES];         // off-diag num per row (2*w_i.sum_{j<i} w_j)
__device__ float g_rowden[N_NODES];         // off-diag den per row
__device__ float g_sspart[1024 * C_DIM];

// ---------------- kAB: fused X-stats + weight folding ----------------
__global__ void kAB(const float* __restrict__ X,
                    const float* __restrict__ Wrel,
                    const float* __restrict__ brel,
                    const float* __restrict__ Wroot,
                    const float* __restrict__ Wmlp,
                    const float* __restrict__ bmlp) {
    int tid = threadIdx.x;
    int b = blockIdx.x;

    if (b < 64) {
        int o = b * 256 + tid;
        int m = o >> 13;
        int r = o & 8191;
        int c = r >> 8;
        int t = r & 255;
        const float* Wx = m ? Wroot : Wrel;
        float acc = 0.f;
        #pragma unroll 8
        for (int f = 0; f < F_DIM; f++)
            acc += Wmlp[c * F_DIM + f] * Wx[f * T_DIM + t];
        if (m) g_W2[c * T_DIM + t] = acc;
        else   g_W1[c * T_DIM + t] = acc;
        return;
    }
    if (b == 64) {
        __shared__ float rs[256];
        __shared__ float WmT[128 * 33];
        int lane = tid & 31, w = tid >> 5;
        for (int o = tid; o < 4096; o += 256) {
            int c = o >> 7, f = o & 127;
            WmT[f * 33 + c] = Wmlp[o];
        }
        const float* src = (w < 4) ? Wrel : Wroot;
        int rbase = (w & 3) * 32;
        for (int r = rbase; r < rbase + 32; r++) {
            float a = 0.f;
            for (int t2 = lane; t2 < T_DIM; t2 += 32) a += src[r * T_DIM + t2];
            for (int o = 16; o > 0; o >>= 1) a += __shfl_xor_sync(0xffffffffu, a, o);
            if (lane == 0) rs[(w < 4 ? 0 : 128) + r] = a;
        }
        __syncthreads();
        if (tid < 96) {
            int c = tid & 31, which = tid >> 5;
            float a = 0.f;
            if (which == 2) {
                for (int f = 0; f < F_DIM; f++) a += WmT[f * 33 + c] * brel[f];
                g_bS[c] = a + bmlp[c];
            } else {
                const float* rsp = rs + which * 128;
                for (int f = 0; f < F_DIM; f++) a += WmT[f * 33 + c] * rsp[f];
                if (which) g_w2sum[c] = a; else g_w1sum[c] = a;
            }
        }
        return;
    }

    int bid = b - 65;
    int g = bid * 256 + tid;
    float s = 0.f, q = 0.f;
    for (int k = g; k < NT_TOT; k += 1024 * 256) {
        float x = X[k];
        s += x; q += x * x;
    }
    __shared__ float ss[256], sq[256];
    ss[tid] = s; sq[tid] = q;
    __syncthreads();
    for (int o = 128; o > 0; o >>= 1) {
        if (tid < o) { ss[tid] += ss[tid + o]; sq[tid] += sq[tid + o]; }
        __syncthreads();
    }
    __shared__ bool isLast;
    if (tid == 0) {
        g_part[bid] = ss[0];
        g_part[1024 + bid] = sq[0];
        __threadfence();
        isLast = (atomicAdd(&g_arr1, 1) == 1023);
    }
    __syncthreads();
    if (!isLast) return;

    float a = 0.f, bb = 0.f;
    #pragma unroll
    for (int u = 0; u < 4; u++) {
        a  += g_part[tid * 4 + u];
        bb += g_part[1024 + tid * 4 + u];
    }
    ss[tid] = a; sq[tid] = bb;
    __syncthreads();
    for (int o = 128; o > 0; o >>= 1) {
        if (tid < o) { ss[tid] += ss[tid + o]; sq[tid] += sq[tid + o]; }
        __syncthreads();
    }
    if (tid == 0) {
        float mu = ss[0] / (float)NT_TOT;
        float var = sq[0] / (float)NT_TOT - mu * mu;
        g_stats[0] = mu;
        g_stats[1] = rsqrtf(var + LN_EPS);
        g_arr1 = 0;
    }
}

// ---------------- K4: Y = Xn@W1^T, Z = Xn@W2^T + bS ----------------
__global__ void k4_yz(const float* __restrict__ X) {
    extern __shared__ float sm[];
    float* W1s = sm;
    float* W2s = sm + 32 * WSTRIDE;
    float* Xs  = sm + 64 * WSTRIDE;
    int tid = threadIdx.x, lane = tid & 31, w = tid >> 5;

    for (int o = tid; o < 8192; o += 256) {
        int c = o >> 8, t = o & 255;
        W1s[c * WSTRIDE + t] = g_W1[o];
        W2s[c * WSTRIDE + t] = g_W2[o];
    }
    int rbase = blockIdx.x * 32;
    const float4* xsrc = (const float4*)(X + (size_t)rbase * T_DIM);
    float4* xd = (float4*)Xs;
    for (int o = tid; o < 2048; o += 256) xd[o] = xsrc[o];
    __syncthreads();

    float mu = g_stats[0], rstd = g_stats[1];
    float aY0 = 0, aY1 = 0, aY2 = 0, aY3 = 0;
    float aZ0 = 0, aZ1 = 0, aZ2 = 0, aZ3 = 0;
    const float* x0 = Xs + (w * 4 + 0) * 256;
    const float* x1 = Xs + (w * 4 + 1) * 256;
    const float* x2 = Xs + (w * 4 + 2) * 256;
    const float* x3 = Xs + (w * 4 + 3) * 256;
    const float* w1p = W1s + lane * WSTRIDE;
    const float* w2p = W2s + lane * WSTRIDE;
    #pragma unroll 4
    for (int t = 0; t < 256; t += 4) {
        float4 w1 = *(const float4*)(w1p + t);
        float4 w2 = *(const float4*)(w2p + t);
        float4 xa = *(const float4*)(x0 + t);
        float4 xb = *(const float4*)(x1 + t);
        float4 xc = *(const float4*)(x2 + t);
        float4 xe = *(const float4*)(x3 + t);
        aY0 += xa.x*w1.x + xa.y*w1.y + xa.z*w1.z + xa.w*w1.w;
        aZ0 += xa.x*w2.x + xa.y*w2.y + xa.z*w2.z + xa.w*w2.w;
        aY1 += xb.x*w1.x + xb.y*w1.y + xb.z*w1.z + xb.w*w1.w;
        aZ1 += xb.x*w2.x + xb.y*w2.y + xb.z*w2.z + xb.w*w2.w;
        aY2 += xc.x*w1.x + xc.y*w1.y + xc.z*w1.z + xc.w*w1.w;
        aZ2 += xc.x*w2.x + xc.y*w2.y + xc.z*w2.z + xc.w*w2.w;
        aY3 += xe.x*w1.x + xe.y*w1.y + xe.z*w1.z + xe.w*w1.w;
        aZ3 += xe.x*w2.x + xe.y*w2.y + xe.z*w2.z + xe.w*w2.w;
    }
    float c1 = mu * g_w1sum[lane];
    float c2 = mu * g_w2sum[lane];
    float bs = g_bS[lane];
    int r0 = rbase + w * 4;
    g_Y[(r0 + 0) * 32 + lane] = rstd * (aY0 - c1);
    g_Y[(r0 + 1) * 32 + lane] = rstd * (aY1 - c1);
    g_Y[(r0 + 2) * 32 + lane] = rstd * (aY2 - c1);
    g_Y[(r0 + 3) * 32 + lane] = rstd * (aY3 - c1);
    g_Z[(r0 + 0) * 32 + lane] = rstd * (aZ0 - c2) + bs;
    g_Z[(r0 + 1) * 32 + lane] = rstd * (aZ1 - c2) + bs;
    g_Z[(r0 + 2) * 32 + lane] = rstd * (aZ2 - c2) + bs;
    g_Z[(r0 + 3) * 32 + lane] = rstd * (aZ3 - c2) + bs;
}

// ---------------- K5a: stream A half -> masks + cnt + dinv ----------------
__global__ void __launch_bounds__(256) k5a(const float* __restrict__ A, int row_base) {
    int i = row_base + blockIdx.x;
    int tid = threadIdx.x, lane = tid & 31, wid = tid >> 5;
    __shared__ int sw[8];

    const float4* arow = (const float4*)(A + (size_t)i * N_NODES);
    unsigned mask = 0;
    #pragma unroll
    for (int u = 0; u < 8; u++) {
        float4 v = __ldcs(&arow[u * 256 + tid]);
        unsigned bb = (v.x != 0.f) | ((v.y != 0.f) << 1) |
                      ((v.z != 0.f) << 2) | ((v.w != 0.f) << 3);
        mask |= bb << (u * 4);
    }
    g_mask[i * 256 + tid] = mask;

    int c = __popc(mask);
    #pragma unroll
    for (int o = 16; o > 0; o >>= 1) c += __shfl_xor_sync(0xffffffffu, c, o);
    if (lane == 0) sw[wid] = c;
    __syncthreads();
    if (tid == 0) {
        int t = 0;
        #pragma unroll
        for (int u = 0; u < 8; u++) t += sw[u];
        if (t > MAXDEG) t = MAXDEG;
        g_cnt[i] = t;
        g_dinv[i] = rsqrtf((float)t);
    }
}

// ---------------- K5b: masks -> gather + softmax + w + aux + diag ----------------
__global__ void __launch_bounds__(256) k5b(float* __restrict__ out, int row_base) {
    int tid = threadIdx.x, lane = tid & 31, w = tid >> 5;
    int i = row_base + blockIdx.x * 8 + w;
    __shared__ __align__(16) int s_idx[8][MAXDEG];

    const int4* mrow = (const int4*)(g_mask + i * 256);
    int4 m0 = mrow[lane * 2];
    int4 m1 = mrow[lane * 2 + 1];
    unsigned ws[8] = { (unsigned)m0.x, (unsigned)m0.y, (unsigned)m0.z, (unsigned)m0.w,
                       (unsigned)m1.x, (unsigned)m1.y, (unsigned)m1.z, (unsigned)m1.w };
    int cL = 0;
    #pragma unroll
    for (int q = 0; q < 8; q++) cL += __popc(ws[q]);

    int incl = cL;
    #pragma unroll
    for (int o = 1; o < 32; o <<= 1) {
        int n = __shfl_up_sync(0xffffffffu, incl, o);
        if (lane >= o) incl += n;
    }
    int p = incl - cL;

    #pragma unroll
    for (int q = 0; q < 8; q++) {
        unsigned m = ws[q];
        int W4 = (lane * 8 + q) << 2;
        while (m) {
            int b = __ffs(m) - 1;
            m &= m - 1;
            int col = ((b >> 2) << 10) + W4 + (b & 3);
            if (p < MAXDEG) s_idx[w][p++] = col;
        }
    }
    __syncwarp();

    int cnt = g_cnt[i];

    float a0 = 0.f, a1 = 0.f, a2 = 0.f, a3 = 0.f;
    float a4 = 0.f, a5 = 0.f, a6 = 0.f, a7 = 0.f;
    int g = 0;
    for (; g + 8 <= cnt; g += 8) {
        const int4* sp = (const int4*)&s_idx[w][g];
        int4 ja = sp[0], jb = sp[1];
        a0 += g_Y[ja.x * 32 + lane];
        a1 += g_Y[ja.y * 32 + lane];
        a2 += g_Y[ja.z * 32 + lane];
        a3 += g_Y[ja.w * 32 + lane];
        a4 += g_Y[jb.x * 32 + lane];
        a5 += g_Y[jb.y * 32 + lane];
        a6 += g_Y[jb.z * 32 + lane];
        a7 += g_Y[jb.w * 32 + lane];
    }
    for (; g < cnt; g++) {
        int j = s_idx[w][g];
        a0 += g_Y[j * 32 + lane];
    }
    float Sv = (((a0 + a1) + (a2 + a3)) + ((a4 + a5) + (a6 + a7))) + g_Z[i * 32 + lane];
    out[(size_t)i * 32 + lane] = Sv;

    float mx = Sv;
    #pragma unroll
    for (int o = 16; o > 0; o >>= 1) mx = fmaxf(mx, __shfl_xor_sync(0xffffffffu, mx, o));
    float e = expf(Sv - mx);
    float ssum = e;
    #pragma unroll
    for (int o = 16; o > 0; o >>= 1) ssum += __shfl_xor_sync(0xffffffffu, ssum, o);
    float sv = e / ssum;
    float di = g_dinv[i];
    g_s[i * 32 + lane] = sv;
    g_w[i * 32 + lane] = di * sv;

    float nsq = sv * sv;
    #pragma unroll
    for (int o = 16; o > 0; o >>= 1) nsq += __shfl_xor_sync(0xffffffffu, nsq, o);
    if (lane == 0) {
        g_aux[i] = make_float2(di, nsq);
        g_diag[i] = di * di * nsq;          // diagonal term (num AND den)
    }
}

// ---------------- triangle walk (shared by k678_lo / k678_hi) ----------------
// rownum_i = 2 * w_i . sum_{j<i in N(i)} w_j
// rowden_i = dinv_i * ( nsq_i * sum_{j<i} dinv_j + sum_{j<i} dinv_j*nsq_j )
__device__ __forceinline__ void tri_row(int i, int w, int lane, int (*s_idx)[MAXDEG]) {
    const int4* mrow = (const int4*)(g_mask + i * 256);
    int4 m0 = mrow[lane * 2];
    int4 m1 = mrow[lane * 2 + 1];
    unsigned ws[8] = { (unsigned)m0.x, (unsigned)m0.y, (unsigned)m0.z, (unsigned)m0.w,
                       (unsigned)m1.x, (unsigned)m1.y, (unsigned)m1.z, (unsigned)m1.w };
    int cLo = 0;
    #pragma unroll
    for (int q = 0; q < 8; q++) {
        unsigned m = ws[q];
        int W4 = (lane * 8 + q) << 2;
        while (m) {
            int bb = __ffs(m) - 1;
            m &= m - 1;
            int col = ((bb >> 2) << 10) + W4 + (bb & 3);
            cLo += (col < i);
        }
    }
    int incl = cLo;
    #pragma unroll
    for (int o = 1; o < 32; o <<= 1) {
        int n = __shfl_up_sync(0xffffffffu, incl, o);
        if (lane >= o) incl += n;
    }
    int p = incl - cLo;
    #pragma unroll
    for (int q = 0; q < 8; q++) {
        unsigned m = ws[q];
        int W4 = (lane * 8 + q) << 2;
        while (m) {
            int bb = __ffs(m) - 1;
            m &= m - 1;
            int col = ((bb >> 2) << 10) + W4 + (bb & 3);
            if (col < i && p < MAXDEG) s_idx[w][p++] = col;
        }
    }
    int cntLo = __shfl_sync(0xffffffffu, incl, 31);
    if (cntLo > MAXDEG) cntLo = MAXDEG;
    __syncwarp();

    float wi = g_w[i * 32 + lane];
    float2 auxI = g_aux[i];
    float di = auxI.x, nsqI = auxI.y;

    float n0 = 0.f, n1 = 0.f, n2 = 0.f, n3 = 0.f;
    float n4 = 0.f, n5 = 0.f, n6 = 0.f, n7 = 0.f;
    int g = 0;
    for (; g + 8 <= cntLo; g += 8) {
        const int4* sp = (const int4*)&s_idx[w][g];
        int4 ja = sp[0], jb = sp[1];
        n0 += g_w[ja.x * 32 + lane];
        n1 += g_w[ja.y * 32 + lane];
        n2 += g_w[ja.z * 32 + lane];
        n3 += g_w[ja.w * 32 + lane];
        n4 += g_w[jb.x * 32 + lane];
        n5 += g_w[jb.y * 32 + lane];
        n6 += g_w[jb.z * 32 + lane];
        n7 += g_w[jb.w * 32 + lane];
    }
    for (; g < cntLo; g++) {
        int j = s_idx[w][g];
        n0 += g_w[j * 32 + lane];
    }
    float an = wi * ((((n0 + n1) + (n2 + n3)) + ((n4 + n5) + (n6 + n7))));

    // aux gathers for den (lane-strided)
    float accA = 0.f, accB = 0.f;
    for (int k = lane; k < cntLo; k += 32) {
        float2 a = g_aux[s_idx[w][k]];
        accA += a.x;
        accB += a.x * a.y;
    }
    #pragma unroll
    for (int o = 16; o > 0; o >>= 1) {
        an   += __shfl_xor_sync(0xffffffffu, an, o);
        accA += __shfl_xor_sync(0xffffffffu, accA, o);
        accB += __shfl_xor_sync(0xffffffffu, accB, o);
    }
    if (lane == 0) {
        g_rownum[i] = 2.f * an;
        g_rowden[i] = di * (nsqI * accA + accB);
    }
}

// ---------------- K678_lo: triangle rows [0,4096) ----------------
__global__ void __launch_bounds__(256) k678_lo() {
    int tid = threadIdx.x, lane = tid & 31, w = tid >> 5;
    __shared__ __align__(16) int s_idx[8][MAXDEG];
    tri_row(blockIdx.x * 8 + w, w, lane, s_idx);
}

// ---------------- K678_hi: triangle rows [4096,8192) + sTs + finalize ----------------
__global__ void __launch_bounds__(256) k678_hi(float* __restrict__ out) {
    int b = blockIdx.x;            // 512 blocks
    int tid = threadIdx.x, lane = tid & 31, w = tid >> 5;
    __shared__ __align__(16) int s_idx[8][MAXDEG];
    tri_row(HALF + b * 8 + w, w, lane, s_idx);

    // ---- sTs: 2 slices per block (c1 = b&31; chunks b>>5 and (b>>5)+16) ----
    int c1 = b & 31;
    __shared__ float red[256];
    #pragma unroll
    for (int half = 0; half < 2; half++) {
        int chunk = (b >> 5) + half * 16;
        float acc = 0.f;
        int iend = chunk * 256 + 256;
        for (int ii = chunk * 256 + w; ii < iend; ii += 8)
            acc += g_s[ii * 32 + c1] * g_s[ii * 32 + lane];
        red[tid] = acc;
        __syncthreads();
        for (int o = 128; o >= 32; o >>= 1) {
            if (tid < o) red[tid] += red[tid + o];
            __syncthreads();
        }
        if (tid < 32) g_sspart[(b + half * 512) * 32 + tid] = red[tid];
        __syncthreads();
    }

    __shared__ bool isLast;
    if (tid == 0) {
        __threadfence();
        isLast = (atomicAdd(&g_arr2, 1) == 511);
    }
    __syncthreads();
    if (!isLast) return;

    // ---- finalize ----
    __shared__ float sd[256];
    __shared__ float s_num, s_den, s_frob;

    float an2 = 0.f, ad2 = 0.f;
    for (int k = tid; k < N_NODES; k += 256) {
        float dg = g_diag[k];
        an2 += g_rownum[k] + dg;
        ad2 += g_rowden[k] + dg;
    }
    sd[tid] = an2;
    __syncthreads();
    for (int o = 128; o > 0; o >>= 1) { if (tid < o) sd[tid] += sd[tid + o]; __syncthreads(); }
    if (tid == 0) s_num = sd[0];
    __syncthreads();
    sd[tid] = ad2;
    __syncthreads();
    for (int o = 128; o > 0; o >>= 1) { if (tid < o) sd[tid] += sd[tid + o]; __syncthreads(); }
    if (tid == 0) s_den = sd[0];
    __syncthreads();

    float ssv[4];
    float fr = 0.f;
    #pragma unroll
    for (int u = 0; u < 4; u++) {
        int e = tid * 4 + u;
        int e1 = e >> 5, e2 = e & 31;
        float v = 0.f;
        #pragma unroll
        for (int ch = 0; ch < 32; ch++)
            v += g_sspart[((ch << 5) | e1) * 32 + e2];
        ssv[u] = v;
        fr += v * v;
    }
    sd[tid] = fr;
    __syncthreads();
    for (int o = 128; o > 0; o >>= 1) { if (tid < o) sd[tid] += sd[tid + o]; __syncthreads(); }
    if (tid == 0) s_frob = sqrtf(sd[0]);
    __syncthreads();

    float dsum = 0.f;
    #pragma unroll
    for (int u = 0; u < 4; u++) {
        int e = tid * 4 + u;
        int e1 = e >> 5, e2 = e & 31;
        float diff = ssv[u] / s_frob - ((e1 == e2) ? rsqrtf((float)C_DIM) : 0.f);
        dsum += diff * diff;
    }
    sd[tid] = dsum;
    __syncthreads();
    for (int o = 128; o > 0; o >>= 1) { if (tid < o) sd[tid] += sd[tid + o]; __syncthreads(); }

    if (tid == 0) {
        out[(size_t)N_NODES * C_DIM + 0] = -(s_num / s_den);
        out[(size_t)N_NODES * C_DIM + 1] = sqrtf(sd[0]);
        g_arr2 = 0;
    }
}

// sTs slice mapping note: slice id for (chunk, c1) is (chunk<<5)|c1; block b stores
// slice b (chunk=b>>5<16) at g_sspart[b*32+..] and slice b+512 (chunk+16) at
// g_sspart[(b+512)*32+..], matching the finalize's ((ch<<5)|e1) indexing.

// ---------------- launch: pipelined halves across two streams ----------------
extern "C" void kernel_launch(void* const* d_in, const int* in_sizes, int n_in,
                              void* d_out, int out_size) {
    const float* X     = (const float*)d_in[0];
    const float* A     = (const float*)d_in[1];
    const float* Wrel  = (const float*)d_in[2];
    const float* brel  = (const float*)d_in[3];
    const float* Wroot = (const float*)d_in[4];
    const float* Wmlp  = (const float*)d_in[5];
    const float* bmlp  = (const float*)d_in[6];
    float* out = (float*)d_out;

    const int K4_SMEM = (64 * WSTRIDE + 8192) * 4;   // 99328 B

    static cudaStream_t s1 = nullptr;
    static cudaEvent_t evF = nullptr, evMlo = nullptr, evY4 = nullptr, evLo = nullptr;
    if (s1 == nullptr) {
        cudaStreamCreateWithFlags(&s1, cudaStreamNonBlocking);
        cudaEventCreateWithFlags(&evF, cudaEventDisableTiming);
        cudaEventCreateWithFlags(&evMlo, cudaEventDisableTiming);
        cudaEventCreateWithFlags(&evY4, cudaEventDisableTiming);
        cudaEventCreateWithFlags(&evLo, cudaEventDisableTiming);
        cudaFuncSetAttribute(k4_yz, cudaFuncAttributeMaxDynamicSharedMemorySize, K4_SMEM);
    }

    // fork
    cudaEventRecord(evF, 0);
    cudaStreamWaitEvent(s1, evF, 0);

    // s1: X-chain
    kAB<<<1089, 256, 0, s1>>>(X, Wrel, brel, Wroot, Wmlp, bmlp);
    k4_yz<<<256, 256, K4_SMEM, s1>>>(X);
    cudaEventRecord(evY4, s1);

    // s0: A first half
    k5a<<<HALF, 256>>>(A, 0);
    cudaEventRecord(evMlo, 0);

    // s1: low-half s-phase (needs k4 + k5a_lo), overlaps k5a_hi
    cudaStreamWaitEvent(s1, evMlo, 0);
    k5b<<<HALF / 8, 256, 0, s1>>>(out, 0);
    k678_lo<<<HALF / 8, 256, 0, s1>>>();
    cudaEventRecord(evLo, s1);

    // s0: A second half, then high-half s-phase
    k5a<<<HALF, 256>>>(A, HALF);
    cudaStreamWaitEvent((cudaStream_t)0, evY4, 0);
    k5b<<<HALF / 8, 256>>>(out, HALF);
    cudaStreamWaitEvent((cudaStream_t)0, evLo, 0);
    k678_hi<<<HALF / 8, 256>>>(out);
}

// round 14
// speedup vs baseline: 1.1020x; 1.1020x over previous
#include <cuda_runtime.h>
#include <cstdint>

// Problem constants
#define N_NODES 8192
#define T_DIM   256
#define F_DIM   128
#define C_DIM   32
#define NT_TOT  (N_NODES * T_DIM)
#define MAXDEG  512
#define LN_EPS  1e-5f
#define WSTRIDE 260

// ---------------- device scratch ----------------
__device__ float g_W1[C_DIM * T_DIM];
__device__ float g_W2[C_DIM * T_DIM];
__device__ float g_bS[C_DIM];
__device__ float g_w1sum[C_DIM];
__device__ float g_w2sum[C_DIM];
__device__ float g_stats[2];
__device__ float g_part[2048];
__device__ int   g_arr1 = 0;
__device__ int   g_arr2 = 0;
__device__ float g_Y[N_NODES * C_DIM];
__device__ float g_Z[N_NODES * C_DIM];
__device__ int   g_nz[(size_t)N_NODES * MAXDEG];
__device__ int   g_cnt[N_NODES];
__device__ float g_dinv[N_NODES];
__device__ float g_nsq[N_NODES];
__device__ float g_s[N_NODES * C_DIM];
__device__ float g_w[N_NODES * C_DIM];      // dinv_j * s_j
__device__ float g_rownum[N_NODES];
__device__ float g_rowden[N_NODES];
__device__ float g_sspart[1024 * C_DIM];

// ---------------- kAB: fused X-stats + weight folding ----------------
__global__ void kAB(const float* __restrict__ X,
                    const float* __restrict__ Wrel,
                    const float* __restrict__ brel,
                    const float* __restrict__ Wroot,
                    const float* __restrict__ Wmlp,
                    const float* __restrict__ bmlp) {
    int tid = threadIdx.x;
    int b = blockIdx.x;

    if (b < 64) {
        int o = b * 256 + tid;
        int m = o >> 13;
        int r = o & 8191;
        int c = r >> 8;
        int t = r & 255;
        const float* Wx = m ? Wroot : Wrel;
        float acc = 0.f;
        #pragma unroll 8
        for (int f = 0; f < F_DIM; f++)
            acc += Wmlp[c * F_DIM + f] * Wx[f * T_DIM + t];
        if (m) g_W2[c * T_DIM + t] = acc;
        else   g_W1[c * T_DIM + t] = acc;
        return;
    }
    if (b == 64) {
        __shared__ float rs[256];
        __shared__ float WmT[128 * 33];
        int lane = tid & 31, w = tid >> 5;
        for (int o = tid; o < 4096; o += 256) {
            int c = o >> 7, f = o & 127;
            WmT[f * 33 + c] = Wmlp[o];
        }
        const float* src = (w < 4) ? Wrel : Wroot;
        int rbase = (w & 3) * 32;
        for (int r = rbase; r < rbase + 32; r++) {
            float a = 0.f;
            for (int t2 = lane; t2 < T_DIM; t2 += 32) a += src[r * T_DIM + t2];
            for (int o = 16; o > 0; o >>= 1) a += __shfl_xor_sync(0xffffffffu, a, o);
            if (lane == 0) rs[(w < 4 ? 0 : 128) + r] = a;
        }
        __syncthreads();
        if (tid < 96) {
            int c = tid & 31, which = tid >> 5;
            float a = 0.f;
            if (which == 2) {
                for (int f = 0; f < F_DIM; f++) a += WmT[f * 33 + c] * brel[f];
                g_bS[c] = a + bmlp[c];
            } else {
                const float* rsp = rs + which * 128;
                for (int f = 0; f < F_DIM; f++) a += WmT[f * 33 + c] * rsp[f];
                if (which) g_w2sum[c] = a; else g_w1sum[c] = a;
            }
        }
        return;
    }

    int bid = b - 65;
    int g = bid * 256 + tid;
    float s = 0.f, q = 0.f;
    for (int k = g; k < NT_TOT; k += 1024 * 256) {
        float x = X[k];
        s += x; q += x * x;
    }
    __shared__ float ss[256], sq[256];
    ss[tid] = s; sq[tid] = q;
    __syncthreads();
    for (int o = 128; o > 0; o >>= 1) {
        if (tid < o) { ss[tid] += ss[tid + o]; sq[tid] += sq[tid + o]; }
        __syncthreads();
    }
    __shared__ bool isLast;
    if (tid == 0) {
        g_part[bid] = ss[0];
        g_part[1024 + bid] = sq[0];
        __threadfence();
        isLast = (atomicAdd(&g_arr1, 1) == 1023);
    }
    __syncthreads();
    if (!isLast) return;

    float a = 0.f, bb = 0.f;
    #pragma unroll
    for (int u = 0; u < 4; u++) {
        a  += g_part[tid * 4 + u];
        bb += g_part[1024 + tid * 4 + u];
    }
    ss[tid] = a; sq[tid] = bb;
    __syncthreads();
    for (int o = 128; o > 0; o >>= 1) {
        if (tid < o) { ss[tid] += ss[tid + o]; sq[tid] += sq[tid + o]; }
        __syncthreads();
    }
    if (tid == 0) {
        float mu = ss[0] / (float)NT_TOT;
        float var = sq[0] / (float)NT_TOT - mu * mu;
        g_stats[0] = mu;
        g_stats[1] = rsqrtf(var + LN_EPS);
        g_arr1 = 0;
    }
}

// ---------------- K4: Y = Xn@W1^T, Z = Xn@W2^T + bS ----------------
__global__ void k4_yz(const float* __restrict__ X) {
    extern __shared__ float sm[];
    float* W1s = sm;
    float* W2s = sm + 32 * WSTRIDE;
    float* Xs  = sm + 64 * WSTRIDE;
    int tid = threadIdx.x, lane = tid & 31, w = tid >> 5;

    for (int o = tid; o < 8192; o += 256) {
        int c = o >> 8, t = o & 255;
        W1s[c * WSTRIDE + t] = g_W1[o];
        W2s[c * WSTRIDE + t] = g_W2[o];
    }
    int rbase = blockIdx.x * 32;
    const float4* xsrc = (const float4*)(X + (size_t)rbase * T_DIM);
    float4* xd = (float4*)Xs;
    for (int o = tid; o < 2048; o += 256) xd[o] = xsrc[o];
    __syncthreads();

    float mu = g_stats[0], rstd = g_stats[1];
    float aY0 = 0, aY1 = 0, aY2 = 0, aY3 = 0;
    float aZ0 = 0, aZ1 = 0, aZ2 = 0, aZ3 = 0;
    const float* x0 = Xs + (w * 4 + 0) * 256;
    const float* x1 = Xs + (w * 4 + 1) * 256;
    const float* x2 = Xs + (w * 4 + 2) * 256;
    const float* x3 = Xs + (w * 4 + 3) * 256;
    const float* w1p = W1s + lane * WSTRIDE;
    const float* w2p = W2s + lane * WSTRIDE;
    #pragma unroll 4
    for (int t = 0; t < 256; t += 4) {
        float4 w1 = *(const float4*)(w1p + t);
        float4 w2 = *(const float4*)(w2p + t);
        float4 xa = *(const float4*)(x0 + t);
        float4 xb = *(const float4*)(x1 + t);
        float4 xc = *(const float4*)(x2 + t);
        float4 xe = *(const float4*)(x3 + t);
        aY0 += xa.x*w1.x + xa.y*w1.y + xa.z*w1.z + xa.w*w1.w;
        aZ0 += xa.x*w2.x + xa.y*w2.y + xa.z*w2.z + xa.w*w2.w;
        aY1 += xb.x*w1.x + xb.y*w1.y + xb.z*w1.z + xb.w*w1.w;
        aZ1 += xb.x*w2.x + xb.y*w2.y + xb.z*w2.z + xb.w*w2.w;
        aY2 += xc.x*w1.x + xc.y*w1.y + xc.z*w1.z + xc.w*w1.w;
        aZ2 += xc.x*w2.x + xc.y*w2.y + xc.z*w2.z + xc.w*w2.w;
        aY3 += xe.x*w1.x + xe.y*w1.y + xe.z*w1.z + xe.w*w1.w;
        aZ3 += xe.x*w2.x + xe.y*w2.y + xe.z*w2.z + xe.w*w2.w;
    }
    float c1 = mu * g_w1sum[lane];
    float c2 = mu * g_w2sum[lane];
    float bs = g_bS[lane];
    int r0 = rbase + w * 4;
    g_Y[(r0 + 0) * 32 + lane] = rstd * (aY0 - c1);
    g_Y[(r0 + 1) * 32 + lane] = rstd * (aY1 - c1);
    g_Y[(r0 + 2) * 32 + lane] = rstd * (aY2 - c1);
    g_Y[(r0 + 3) * 32 + lane] = rstd * (aY3 - c1);
    g_Z[(r0 + 0) * 32 + lane] = rstd * (aZ0 - c2) + bs;
    g_Z[(r0 + 1) * 32 + lane] = rstd * (aZ1 - c2) + bs;
    g_Z[(r0 + 2) * 32 + lane] = rstd * (aZ2 - c2) + bs;
    g_Z[(r0 + 3) * 32 + lane] = rstd * (aZ3 - c2) + bs;
}

// ---------------- K5main: fused stream A + CSR + gather + softmax + w/nsq ----------------
// One block per row. Gather hides under the streaming loads of other blocks (R4: 52.6us).
__global__ void __launch_bounds__(256) k5main(const float* __restrict__ A,
                                              float* __restrict__ out) {
    int i = blockIdx.x;
    int tid = threadIdx.x, lane = tid & 31, wid = tid >> 5;
    __shared__ int s_idx[MAXDEG];
    __shared__ int s_warp[8];
    __shared__ int s_total;
    __shared__ float s_red[256];

    // stream this row of A (coalesced, evict-first)
    const float4* arow = (const float4*)(A + (size_t)i * N_NODES);
    unsigned mask = 0;
    #pragma unroll
    for (int u = 0; u < 8; u++) {
        float4 v = __ldcs(&arow[u * 256 + tid]);
        unsigned bb = (v.x != 0.f) | ((v.y != 0.f) << 1) |
                      ((v.z != 0.f) << 2) | ((v.w != 0.f) << 3);
        mask |= bb << (u * 4);
    }
    int cntL = __popc(mask);

    // deterministic block scan
    int incl = cntL;
    for (int o = 1; o < 32; o <<= 1) {
        int n = __shfl_up_sync(0xffffffffu, incl, o);
        if (lane >= o) incl += n;
    }
    if (lane == 31) s_warp[wid] = incl;
    __syncthreads();
    if (tid < 8) {
        int wv = s_warp[tid];
        int inc = wv;
        for (int o = 1; o < 8; o <<= 1) {
            int n = __shfl_up_sync(0xffu, inc, o);
            if (tid >= o) inc += n;
        }
        if (tid == 7) s_total = inc;
        s_warp[tid] = inc - wv;
    }
    __syncthreads();

    int p = s_warp[wid] + (incl - cntL);
    unsigned m = mask;
    while (m) {
        int bb = __ffs(m) - 1;
        m &= m - 1;
        int col = ((bb >> 2) << 10) + (tid << 2) + (bb & 3);
        if (p < MAXDEG) s_idx[p++] = col;
    }
    __syncthreads();

    int total = s_total;
    if (total > MAXDEG) total = MAXDEG;
    float dinv = rsqrtf((float)total);          // A is 0/1: degree == nnz
    if (tid == 0) { g_cnt[i] = total; g_dinv[i] = dinv; }

    // write CSR row for k678
    for (int k = tid; k < total; k += 256)
        g_nz[(size_t)i * MAXDEG + k] = s_idx[k];

    // gather: 8 warps, stride-8 edges, lane=channel
    float acc = 0.f;
    #pragma unroll 2
    for (int k = wid; k < total; k += 8) {
        int j = s_idx[k];
        acc += g_Y[j * 32 + lane];
    }
    s_red[wid * 32 + lane] = acc;
    __syncthreads();

    if (tid < 32) {
        float Sv = g_Z[i * 32 + tid];
        #pragma unroll
        for (int w = 0; w < 8; w++) Sv += s_red[w * 32 + tid];
        out[(size_t)i * 32 + tid] = Sv;         // output S

        float mx = Sv;
        #pragma unroll
        for (int o = 16; o > 0; o >>= 1) mx = fmaxf(mx, __shfl_xor_sync(0xffffffffu, mx, o));
        float e = expf(Sv - mx);
        float ssum = e;
        #pragma unroll
        for (int o = 16; o > 0; o >>= 1) ssum += __shfl_xor_sync(0xffffffffu, ssum, o);
        float sv = e / ssum;
        g_s[i * 32 + tid] = sv;
        g_w[i * 32 + tid] = dinv * sv;

        float nsq = sv * sv;
        #pragma unroll
        for (int o = 16; o > 0; o >>= 1) nsq += __shfl_xor_sync(0xffffffffu, nsq, o);
        if (tid == 0) g_nsq[i] = nsq;
    }
}

// ---------------- K678: rownum/rowden + s^T s partials + finalize ----------------
// rownum_i = dinv_i * s_i . (sum_{j in N(i)} w_j)        (self-loop included)
// rowden_i = dinv_i * (sum_{j in N(i)} dinv_j) * nsq_i
__global__ void __launch_bounds__(256) k678(float* __restrict__ out) {
    int b = blockIdx.x;
    int tid = threadIdx.x, lane = tid & 31, w = tid >> 5;

    int i = b * 8 + w;
    float si = g_s[i * 32 + lane];
    float di = g_dinv[i];
    float nsqI = g_nsq[i];
    int cnt = g_cnt[i];
    const size_t base = (size_t)i * MAXDEG;
    float n0 = 0.f, n1 = 0.f, n2 = 0.f, n3 = 0.f;
    float n4 = 0.f, n5 = 0.f, n6 = 0.f, n7 = 0.f;
    float accd = 0.f;

    for (int kk = 0; kk < cnt; kk += 32) {
        int rem = cnt - kk; if (rem > 32) rem = 32;
        int valid = (kk + lane) < cnt;
        int idx = valid ? g_nz[base + kk + lane] : 0;
        accd += valid ? g_dinv[idx] : 0.f;
        int g = 0;
        for (; g + 8 <= rem; g += 8) {
            int j0 = __shfl_sync(0xffffffffu, idx, g + 0);
            int j1 = __shfl_sync(0xffffffffu, idx, g + 1);
            int j2 = __shfl_sync(0xffffffffu, idx, g + 2);
            int j3 = __shfl_sync(0xffffffffu, idx, g + 3);
            int j4 = __shfl_sync(0xffffffffu, idx, g + 4);
            int j5 = __shfl_sync(0xffffffffu, idx, g + 5);
            int j6 = __shfl_sync(0xffffffffu, idx, g + 6);
            int j7 = __shfl_sync(0xffffffffu, idx, g + 7);
            n0 += g_w[j0 * 32 + lane];
            n1 += g_w[j1 * 32 + lane];
            n2 += g_w[j2 * 32 + lane];
            n3 += g_w[j3 * 32 + lane];
            n4 += g_w[j4 * 32 + lane];
            n5 += g_w[j5 * 32 + lane];
            n6 += g_w[j6 * 32 + lane];
            n7 += g_w[j7 * 32 + lane];
        }
        for (; g < rem; g++) {
            int j = __shfl_sync(0xffffffffu, idx, g);
            n0 += g_w[j * 32 + lane];
        }
    }
    float an = si * ((((n0 + n1) + (n2 + n3)) + ((n4 + n5) + (n6 + n7))));
    #pragma unroll
    for (int o = 16; o > 0; o >>= 1) {
        an   += __shfl_xor_sync(0xffffffffu, an, o);
        accd += __shfl_xor_sync(0xffffffffu, accd, o);
    }
    if (lane == 0) {
        g_rownum[i] = di * an;
        g_rowden[i] = di * accd * nsqI;
    }

    // ---- sTs partial: (c1, chunk) slice over 256 rows ----
    int c1 = b & 31, chunk = b >> 5;
    float acc = 0.f;
    int iend = chunk * 256 + 256;
    for (int ii = chunk * 256 + w; ii < iend; ii += 8)
        acc += g_s[ii * 32 + c1] * g_s[ii * 32 + lane];
    __shared__ float red[256];
    red[tid] = acc;
    __syncthreads();
    for (int o = 128; o >= 32; o >>= 1) {
        if (tid < o) red[tid] += red[tid + o];
        __syncthreads();
    }
    if (tid < 32) g_sspart[b * 32 + tid] = red[tid];

    __shared__ bool isLast;
    if (tid == 0) {
        __threadfence();
        isLast = (atomicAdd(&g_arr2, 1) == 1023);
    }
    __syncthreads();
    if (!isLast) return;

    // ---- finalize ----
    __shared__ float sd[256];
    __shared__ float s_num, s_den, s_frob;

    float an2 = 0.f, ad2 = 0.f;
    for (int k = tid; k < N_NODES; k += 256) {
        an2 += g_rownum[k];
        ad2 += g_rowden[k];
    }
    sd[tid] = an2;
    __syncthreads();
    for (int o = 128; o > 0; o >>= 1) { if (tid < o) sd[tid] += sd[tid + o]; __syncthreads(); }
    if (tid == 0) s_num = sd[0];
    __syncthreads();
    sd[tid] = ad2;
    __syncthreads();
    for (int o = 128; o > 0; o >>= 1) { if (tid < o) sd[tid] += sd[tid + o]; __syncthreads(); }
    if (tid == 0) s_den = sd[0];
    __syncthreads();

    float ssv[4];
    float fr = 0.f;
    #pragma unroll
    for (int u = 0; u < 4; u++) {
        int e = tid * 4 + u;
        int e1 = e >> 5, e2 = e & 31;
        float v = 0.f;
        #pragma unroll
        for (int ch = 0; ch < 32; ch++)
            v += g_sspart[((ch << 5) | e1) * 32 + e2];
        ssv[u] = v;
        fr += v * v;
    }
    sd[tid] = fr;
    __syncthreads();
    for (int o = 128; o > 0; o >>= 1) { if (tid < o) sd[tid] += sd[tid + o]; __syncthreads(); }
    if (tid == 0) s_frob = sqrtf(sd[0]);
    __syncthreads();

    float dsum = 0.f;
    #pragma unroll
    for (int u = 0; u < 4; u++) {
        int e = tid * 4 + u;
        int e1 = e >> 5, e2 = e & 31;
        float diff = ssv[u] / s_frob - ((e1 == e2) ? rsqrtf((float)C_DIM) : 0.f);
        dsum += diff * diff;
    }
    sd[tid] = dsum;
    __syncthreads();
    for (int o = 128; o > 0; o >>= 1) { if (tid < o) sd[tid] += sd[tid + o]; __syncthreads(); }

    if (tid == 0) {
        out[(size_t)N_NODES * C_DIM + 0] = -(s_num / s_den);   // loss_mc
        out[(size_t)N_NODES * C_DIM + 1] = sqrtf(sd[0]);       // loss_o
        g_arr2 = 0;
    }
}

// ---------------- launch: single stream, 4 kernels ----------------
extern "C" void kernel_launch(void* const* d_in, const int* in_sizes, int n_in,
                              void* d_out, int out_size) {
    const float* X     = (const float*)d_in[0];
    const float* A     = (const float*)d_in[1];
    const float* Wrel  = (const float*)d_in[2];
    const float* brel  = (const float*)d_in[3];
    const float* Wroot = (const float*)d_in[4];
    const float* Wmlp  = (const float*)d_in[5];
    const float* bmlp  = (const float*)d_in[6];
    float* out = (float*)d_out;

    const int K4_SMEM = (64 * WSTRIDE + 8192) * 4;   // 99328 B

    static bool init = false;
    if (!init) {
        cudaFuncSetAttribute(k4_yz, cudaFuncAttributeMaxDynamicSharedMemorySize, K4_SMEM);
        init = true;
    }

    kAB<<<1089, 256>>>(X, Wrel, brel, Wroot, Wmlp, bmlp);
    k4_yz<<<256, 256, K4_SMEM>>>(X);
    k5main<<<N_NODES, 256>>>(A, out);
    k678<<<1024, 256>>>(out);
}

// round 15
// speedup vs baseline: 1.1045x; 1.0022x over previous
#include <cuda_runtime.h>
#include <cstdint>

// Problem constants
#define N_NODES 8192
#define T_DIM   256
#define F_DIM   128
#define C_DIM   32
#define NT_TOT  (N_NODES * T_DIM)
#define MAXDEG  512
#define LN_EPS  1e-5f
#define WSTRIDE 260

// ---------------- device scratch ----------------
__device__ float g_W1[C_DIM * T_DIM];
__device__ float g_W2[C_DIM * T_DIM];
__device__ float g_bS[C_DIM];
__device__ float g_w1sum[C_DIM];
__device__ float g_w2sum[C_DIM];
__device__ float g_stats[2];
__device__ float g_part[2048];
__device__ int   g_arr1 = 0;
__device__ int   g_arr2 = 0;
__device__ float g_Y[N_NODES * C_DIM];
__device__ float g_Z[N_NODES * C_DIM];
__device__ int   g_nz[(size_t)N_NODES * MAXDEG];
__device__ int   g_cnt[N_NODES];
__device__ float g_dinv[N_NODES];
__device__ float g_nsq[N_NODES];
__device__ float g_s[N_NODES * C_DIM];
__device__ float g_w[N_NODES * C_DIM];      // dinv_j * s_j
__device__ float g_rownum[N_NODES];
__device__ float g_rowden[N_NODES];
__device__ float g_sspart[1024 * C_DIM];

// ---------------- kAB: fused X-stats + weight folding ----------------
__global__ void kAB(const float* __restrict__ X,
                    const float* __restrict__ Wrel,
                    const float* __restrict__ brel,
                    const float* __restrict__ Wroot,
                    const float* __restrict__ Wmlp,
                    const float* __restrict__ bmlp) {
    int tid = threadIdx.x;
    int b = blockIdx.x;

    if (b < 64) {
        int o = b * 256 + tid;
        int m = o >> 13;
        int r = o & 8191;
        int c = r >> 8;
        int t = r & 255;
        const float* Wx = m ? Wroot : Wrel;
        float acc = 0.f;
        #pragma unroll 8
        for (int f = 0; f < F_DIM; f++)
            acc += Wmlp[c * F_DIM + f] * Wx[f * T_DIM + t];
        if (m) g_W2[c * T_DIM + t] = acc;
        else   g_W1[c * T_DIM + t] = acc;
        return;
    }
    if (b == 64) {
        __shared__ float rs[256];
        __shared__ float WmT[128 * 33];
        int lane = tid & 31, w = tid >> 5;
        for (int o = tid; o < 4096; o += 256) {
            int c = o >> 7, f = o & 127;
            WmT[f * 33 + c] = Wmlp[o];
        }
        const float* src = (w < 4) ? Wrel : Wroot;
        int rbase = (w & 3) * 32;
        for (int r = rbase; r < rbase + 32; r++) {
            float a = 0.f;
            for (int t2 = lane; t2 < T_DIM; t2 += 32) a += src[r * T_DIM + t2];
            for (int o = 16; o > 0; o >>= 1) a += __shfl_xor_sync(0xffffffffu, a, o);
            if (lane == 0) rs[(w < 4 ? 0 : 128) + r] = a;
        }
        __syncthreads();
        if (tid < 96) {
            int c = tid & 31, which = tid >> 5;
            float a = 0.f;
            if (which == 2) {
                for (int f = 0; f < F_DIM; f++) a += WmT[f * 33 + c] * brel[f];
                g_bS[c] = a + bmlp[c];
            } else {
                const float* rsp = rs + which * 128;
                for (int f = 0; f < F_DIM; f++) a += WmT[f * 33 + c] * rsp[f];
                if (which) g_w2sum[c] = a; else g_w1sum[c] = a;
            }
        }
        return;
    }

    int bid = b - 65;
    int g = bid * 256 + tid;
    float s = 0.f, q = 0.f;
    for (int k = g; k < NT_TOT; k += 1024 * 256) {
        float x = X[k];
        s += x; q += x * x;
    }
    __shared__ float ss[256], sq[256];
    ss[tid] = s; sq[tid] = q;
    __syncthreads();
    for (int o = 128; o > 0; o >>= 1) {
        if (tid < o) { ss[tid] += ss[tid + o]; sq[tid] += sq[tid + o]; }
        __syncthreads();
    }
    __shared__ bool isLast;
    if (tid == 0) {
        g_part[bid] = ss[0];
        g_part[1024 + bid] = sq[0];
        __threadfence();
        isLast = (atomicAdd(&g_arr1, 1) == 1023);
    }
    __syncthreads();
    if (!isLast) return;

    float a = 0.f, bb = 0.f;
    #pragma unroll
    for (int u = 0; u < 4; u++) {
        a  += g_part[tid * 4 + u];
        bb += g_part[1024 + tid * 4 + u];
    }
    ss[tid] = a; sq[tid] = bb;
    __syncthreads();
    for (int o = 128; o > 0; o >>= 1) {
        if (tid < o) { ss[tid] += ss[tid + o]; sq[tid] += sq[tid + o]; }
        __syncthreads();
    }
    if (tid == 0) {
        float mu = ss[0] / (float)NT_TOT;
        float var = sq[0] / (float)NT_TOT - mu * mu;
        g_stats[0] = mu;
        g_stats[1] = rsqrtf(var + LN_EPS);
        g_arr1 = 0;
    }
}

// ---------------- K4: Y = Xn@W1^T, Z = Xn@W2^T + bS ----------------
__global__ void k4_yz(const float* __restrict__ X) {
    extern __shared__ float sm[];
    float* W1s = sm;
    float* W2s = sm + 32 * WSTRIDE;
    float* Xs  = sm + 64 * WSTRIDE;
    int tid = threadIdx.x, lane = tid & 31, w = tid >> 5;

    for (int o = tid; o < 8192; o += 256) {
        int c = o >> 8, t = o & 255;
        W1s[c * WSTRIDE + t] = g_W1[o];
        W2s[c * WSTRIDE + t] = g_W2[o];
    }
    int rbase = blockIdx.x * 32;
    const float4* xsrc = (const float4*)(X + (size_t)rbase * T_DIM);
    float4* xd = (float4*)Xs;
    for (int o = tid; o < 2048; o += 256) xd[o] = xsrc[o];
    __syncthreads();

    float mu = g_stats[0], rstd = g_stats[1];
    float aY0 = 0, aY1 = 0, aY2 = 0, aY3 = 0;
    float aZ0 = 0, aZ1 = 0, aZ2 = 0, aZ3 = 0;
    const float* x0 = Xs + (w * 4 + 0) * 256;
    const float* x1 = Xs + (w * 4 + 1) * 256;
    const float* x2 = Xs + (w * 4 + 2) * 256;
    const float* x3 = Xs + (w * 4 + 3) * 256;
    const float* w1p = W1s + lane * WSTRIDE;
    const float* w2p = W2s + lane * WSTRIDE;
    #pragma unroll 4
    for (int t = 0; t < 256; t += 4) {
        float4 w1 = *(const float4*)(w1p + t);
        float4 w2 = *(const float4*)(w2p + t);
        float4 xa = *(const float4*)(x0 + t);
        float4 xb = *(const float4*)(x1 + t);
        float4 xc = *(const float4*)(x2 + t);
        float4 xe = *(const float4*)(x3 + t);
        aY0 += xa.x*w1.x + xa.y*w1.y + xa.z*w1.z + xa.w*w1.w;
        aZ0 += xa.x*w2.x + xa.y*w2.y + xa.z*w2.z + xa.w*w2.w;
        aY1 += xb.x*w1.x + xb.y*w1.y + xb.z*w1.z + xb.w*w1.w;
        aZ1 += xb.x*w2.x + xb.y*w2.y + xb.z*w2.z + xb.w*w2.w;
        aY2 += xc.x*w1.x + xc.y*w1.y + xc.z*w1.z + xc.w*w1.w;
        aZ2 += xc.x*w2.x + xc.y*w2.y + xc.z*w2.z + xc.w*w2.w;
        aY3 += xe.x*w1.x + xe.y*w1.y + xe.z*w1.z + xe.w*w1.w;
        aZ3 += xe.x*w2.x + xe.y*w2.y + xe.z*w2.z + xe.w*w2.w;
    }
    float c1 = mu * g_w1sum[lane];
    float c2 = mu * g_w2sum[lane];
    float bs = g_bS[lane];
    int r0 = rbase + w * 4;
    g_Y[(r0 + 0) * 32 + lane] = rstd * (aY0 - c1);
    g_Y[(r0 + 1) * 32 + lane] = rstd * (aY1 - c1);
    g_Y[(r0 + 2) * 32 + lane] = rstd * (aY2 - c1);
    g_Y[(r0 + 3) * 32 + lane] = rstd * (aY3 - c1);
    g_Z[(r0 + 0) * 32 + lane] = rstd * (aZ0 - c2) + bs;
    g_Z[(r0 + 1) * 32 + lane] = rstd * (aZ1 - c2) + bs;
    g_Z[(r0 + 2) * 32 + lane] = rstd * (aZ2 - c2) + bs;
    g_Z[(r0 + 3) * 32 + lane] = rstd * (aZ3 - c2) + bs;
}

// ---------------- K5main: fused stream A + CSR + gather + softmax + w/nsq ----------------
__global__ void __launch_bounds__(256) k5main(const float* __restrict__ A,
                                              float* __restrict__ out) {
    int i = blockIdx.x;
    int tid = threadIdx.x, lane = tid & 31, wid = tid >> 5;
    __shared__ int s_idx[MAXDEG];
    __shared__ int s_warp[8];
    __shared__ int s_total;
    __shared__ float s_red[256];

    const float4* arow = (const float4*)(A + (size_t)i * N_NODES);
    unsigned mask = 0;
    #pragma unroll
    for (int u = 0; u < 8; u++) {
        float4 v = __ldcs(&arow[u * 256 + tid]);
        unsigned bb = (v.x != 0.f) | ((v.y != 0.f) << 1) |
                      ((v.z != 0.f) << 2) | ((v.w != 0.f) << 3);
        mask |= bb << (u * 4);
    }
    int cntL = __popc(mask);

    int incl = cntL;
    for (int o = 1; o < 32; o <<= 1) {
        int n = __shfl_up_sync(0xffffffffu, incl, o);
        if (lane >= o) incl += n;
    }
    if (lane == 31) s_warp[wid] = incl;
    __syncthreads();
    if (tid < 8) {
        int wv = s_warp[tid];
        int inc = wv;
        for (int o = 1; o < 8; o <<= 1) {
            int n = __shfl_up_sync(0xffu, inc, o);
            if (tid >= o) inc += n;
        }
        if (tid == 7) s_total = inc;
        s_warp[tid] = inc - wv;
    }
    __syncthreads();

    int p = s_warp[wid] + (incl - cntL);
    unsigned m = mask;
    while (m) {
        int bb = __ffs(m) - 1;
        m &= m - 1;
        int col = ((bb >> 2) << 10) + (tid << 2) + (bb & 3);
        if (p < MAXDEG) s_idx[p++] = col;
    }
    __syncthreads();

    int total = s_total;
    if (total > MAXDEG) total = MAXDEG;
    float dinv = rsqrtf((float)total);
    if (tid == 0) { g_cnt[i] = total; g_dinv[i] = dinv; }

    for (int k = tid; k < total; k += 256)
        g_nz[(size_t)i * MAXDEG + k] = s_idx[k];

    float acc = 0.f;
    #pragma unroll 2
    for (int k = wid; k < total; k += 8) {
        int j = s_idx[k];
        acc += g_Y[j * 32 + lane];
    }
    s_red[wid * 32 + lane] = acc;
    __syncthreads();

    if (tid < 32) {
        float Sv = g_Z[i * 32 + tid];
        #pragma unroll
        for (int w = 0; w < 8; w++) Sv += s_red[w * 32 + tid];
        out[(size_t)i * 32 + tid] = Sv;

        float mx = Sv;
        #pragma unroll
        for (int o = 16; o > 0; o >>= 1) mx = fmaxf(mx, __shfl_xor_sync(0xffffffffu, mx, o));
        float e = expf(Sv - mx);
        float ssum = e;
        #pragma unroll
        for (int o = 16; o > 0; o >>= 1) ssum += __shfl_xor_sync(0xffffffffu, ssum, o);
        float sv = e / ssum;
        g_s[i * 32 + tid] = sv;
        g_w[i * 32 + tid] = dinv * sv;

        float nsq = sv * sv;
        #pragma unroll
        for (int o = 16; o > 0; o >>= 1) nsq += __shfl_xor_sync(0xffffffffu, nsq, o);
        if (tid == 0) g_nsq[i] = nsq;
    }
}

// ---------------- K678: triangle rownum/rowden (CSR compaction) + sTs + finalize ----------------
// rownum_i = sum_lane [ w_i * 2*sum_{j<i in N(i)} w_j + w_i^2 ]   (symmetric mask, self-loop)
// rowden_i = dinv_i * (sum_{j in N(i)} dinv_j) * nsq_i
__global__ void __launch_bounds__(256) k678(float* __restrict__ out) {
    int b = blockIdx.x;
    int tid = threadIdx.x, lane = tid & 31, w = tid >> 5;
    __shared__ __align__(16) int s_cmp[8][MAXDEG];

    int i = b * 8 + w;
    float wi = g_w[i * 32 + lane];
    float di = g_dinv[i];
    float nsqI = g_nsq[i];
    int cnt = g_cnt[i];
    const size_t base = (size_t)i * MAXDEG;

    // pass 1: full-neighbor dinv sum + compact indices j<i into smem
    float accd = 0.f;
    int cLo = 0;
    for (int kk = 0; kk < cnt; kk += 32) {
        int valid = (kk + lane) < cnt;
        int idx = valid ? g_nz[base + kk + lane] : 0;
        accd += valid ? g_dinv[idx] : 0.f;
        unsigned bal = __ballot_sync(0xffffffffu, valid && (idx < i));
        if (valid && idx < i) {
            int pos = cLo + __popc(bal & ((1u << lane) - 1u));
            s_cmp[w][pos] = idx;
        }
        cLo += __popc(bal);
    }
    __syncwarp();

    // pass 2: walk compacted (halved) edge list, 8-deep ILP
    float n0 = 0.f, n1 = 0.f, n2 = 0.f, n3 = 0.f;
    float n4 = 0.f, n5 = 0.f, n6 = 0.f, n7 = 0.f;
    int g = 0;
    for (; g + 8 <= cLo; g += 8) {
        const int4* sp = (const int4*)&s_cmp[w][g];
        int4 ja = sp[0], jb = sp[1];
        n0 += g_w[ja.x * 32 + lane];
        n1 += g_w[ja.y * 32 + lane];
        n2 += g_w[ja.z * 32 + lane];
        n3 += g_w[ja.w * 32 + lane];
        n4 += g_w[jb.x * 32 + lane];
        n5 += g_w[jb.y * 32 + lane];
        n6 += g_w[jb.z * 32 + lane];
        n7 += g_w[jb.w * 32 + lane];
    }
    for (; g < cLo; g++) {
        int j = s_cmp[w][g];
        n0 += g_w[j * 32 + lane];
    }
    float sumw = (((n0 + n1) + (n2 + n3)) + ((n4 + n5) + (n6 + n7)));
    float an = wi * (2.f * sumw + wi);      // includes self-loop diagonal wi^2
    #pragma unroll
    for (int o = 16; o > 0; o >>= 1) {
        an   += __shfl_xor_sync(0xffffffffu, an, o);
        accd += __shfl_xor_sync(0xffffffffu, accd, o);
    }
    if (lane == 0) {
        g_rownum[i] = an;
        g_rowden[i] = di * accd * nsqI;
    }

    // ---- sTs partial: (c1, chunk) slice over 256 rows ----
    int c1 = b & 31, chunk = b >> 5;
    float acc = 0.f;
    int iend = chunk * 256 + 256;
    for (int ii = chunk * 256 + w; ii < iend; ii += 8)
        acc += g_s[ii * 32 + c1] * g_s[ii * 32 + lane];
    __shared__ float red[256];
    red[tid] = acc;
    __syncthreads();
    for (int o = 128; o >= 32; o >>= 1) {
        if (tid < o) red[tid] += red[tid + o];
        __syncthreads();
    }
    if (tid < 32) g_sspart[b * 32 + tid] = red[tid];

    __shared__ bool isLast;
    if (tid == 0) {
        __threadfence();
        isLast = (atomicAdd(&g_arr2, 1) == 1023);
    }
    __syncthreads();
    if (!isLast) return;

    // ---- finalize ----
    __shared__ float sd[256];
    __shared__ float s_num, s_den, s_frob;

    float an2 = 0.f, ad2 = 0.f;
    for (int k = tid; k < N_NODES; k += 256) {
        an2 += g_rownum[k];
        ad2 += g_rowden[k];
    }
    sd[tid] = an2;
    __syncthreads();
    for (int o = 128; o > 0; o >>= 1) { if (tid < o) sd[tid] += sd[tid + o]; __syncthreads(); }
    if (tid == 0) s_num = sd[0];
    __syncthreads();
    sd[tid] = ad2;
    __syncthreads();
    for (int o = 128; o > 0; o >>= 1) { if (tid < o) sd[tid] += sd[tid + o]; __syncthreads(); }
    if (tid == 0) s_den = sd[0];
    __syncthreads();

    float ssv[4];
    float fr = 0.f;
    #pragma unroll
    for (int u = 0; u < 4; u++) {
        int e = tid * 4 + u;
        int e1 = e >> 5, e2 = e & 31;
        float v = 0.f;
        #pragma unroll
        for (int ch = 0; ch < 32; ch++)
            v += g_sspart[((ch << 5) | e1) * 32 + e2];
        ssv[u] = v;
        fr += v * v;
    }
    sd[tid] = fr;
    __syncthreads();
    for (int o = 128; o > 0; o >>= 1) { if (tid < o) sd[tid] += sd[tid + o]; __syncthreads(); }
    if (tid == 0) s_frob = sqrtf(sd[0]);
    __syncthreads();

    float dsum = 0.f;
    #pragma unroll
    for (int u = 0; u < 4; u++) {
        int e = tid * 4 + u;
        int e1 = e >> 5, e2 = e & 31;
        float diff = ssv[u] / s_frob - ((e1 == e2) ? rsqrtf((float)C_DIM) : 0.f);
        dsum += diff * diff;
    }
    sd[tid] = dsum;
    __syncthreads();
    for (int o = 128; o > 0; o >>= 1) { if (tid < o) sd[tid] += sd[tid + o]; __syncthreads(); }

    if (tid == 0) {
        out[(size_t)N_NODES * C_DIM + 0] = -(s_num / s_den);   // loss_mc
        out[(size_t)N_NODES * C_DIM + 1] = sqrtf(sd[0]);       // loss_o
        g_arr2 = 0;
    }
}

// ---------------- launch: single stream, 4 kernels ----------------
extern "C" void kernel_launch(void* const* d_in, const int* in_sizes, int n_in,
                              void* d_out, int out_size) {
    const float* X     = (const float*)d_in[0];
    const float* A     = (const float*)d_in[1];
    const float* Wrel  = (const float*)d_in[2];
    const float* brel  = (const float*)d_in[3];
    const float* Wroot = (const float*)d_in[4];
    const float* Wmlp  = (const float*)d_in[5];
    const float* bmlp  = (const float*)d_in[6];
    float* out = (float*)d_out;

    const int K4_SMEM = (64 * WSTRIDE + 8192) * 4;   // 99328 B

    static bool init = false;
    if (!init) {
        cudaFuncSetAttribute(k4_yz, cudaFuncAttributeMaxDynamicSharedMemorySize, K4_SMEM);
        init = true;
    }

    kAB<<<1089, 256>>>(X, Wrel, brel, Wroot, Wmlp, bmlp);
    k4_yz<<<256, 256, K4_SMEM>>>(X);
    k5main<<<N_NODES, 256>>>(A, out);
    k678<<<1024, 256>>>(out);
}